// round 10
// baseline (speedup 1.0000x reference)
#include <cuda_runtime.h>

// RepeatDecoder: B=1024, S=200, H=128, VOCAB=100000
//   features = tanh(hidden + hidden[:,0:1,:])
//   scores   = features @ w_proj + b_proj ; mask PAD/INTEREST -> -inf
//   attn     = softmax(scores, axis=-1)
//   out[b, input_ids[b,s]] += attn[b,s]   (out zero elsewhere)
//
// R10: run the 409.6 MB memset (driver fill path, ~6.9 TB/s, likely copy
//      engine) CONCURRENTLY with the score/softmax compute kernel via a
//      fork-join captured side stream. Scatter joins after both.
//
//        main:  [fork ev] -- compute->g_wgt --------\
//        side:       \-- memset(out) -- [join ev] -- scatter(out)

#define RD_VOCAB 100000
#define RD_PAD_ID (RD_VOCAB - 2)
#define RD_INTEREST_ID (RD_VOCAB - 1)
#define RD_B 1024
#define RD_S 200
#define RD_H 128
#define RD_THREADS 256
#define RD_WARPS (RD_THREADS / 32)

// Scratch: per-position attention weights (0 for masked). 800 KB, static.
__device__ float g_wgt[RD_B * RD_S];

__device__ __forceinline__ float fast_tanhf(float x) {
    float r;
    asm("tanh.approx.f32 %0, %1;" : "=f"(r) : "f"(x));
    return r;
}

// ---------------------------------------------------------------------------
// Compute: scores -> softmax -> g_wgt. Never touches `out` (runs under memset).
// ---------------------------------------------------------------------------
__global__ __launch_bounds__(RD_THREADS)
void rd_compute_kernel(const float* __restrict__ hidden,
                       const int* __restrict__ ids,
                       const float* __restrict__ w_proj,
                       const float* __restrict__ b_proj)
{
    __shared__ float s_scores[RD_S];
    __shared__ float s_part[RD_WARPS];
    __shared__ float s_bcast;

    const int b    = blockIdx.x;
    const int tid  = threadIdx.x;
    const int warp = tid >> 5;
    const int lane = tid & 31;

    const float* hb = hidden + (size_t)b * RD_S * RD_H;

    const float4 w4 = reinterpret_cast<const float4*>(w_proj)[lane];
    const float4 k4 = reinterpret_cast<const float4*>(hb)[lane];
    const float  bias = b_proj[0];

    // Two positions per warp per iteration: s0 = it*16+warp, s1 = s0+8.
    #pragma unroll 1
    for (int it = 0; it < 13; ++it) {
        const int s0 = it * 16 + warp;
        const int s1 = s0 + 8;
        const bool has1 = (s1 < RD_S);

        const float4 h0 = reinterpret_cast<const float4*>(hb + s0 * RD_H)[lane];
        float4 h1;
        if (has1) h1 = reinterpret_cast<const float4*>(hb + s1 * RD_H)[lane];

        float p0 = fast_tanhf(h0.x + k4.x) * w4.x;
        p0 = fmaf(fast_tanhf(h0.y + k4.y), w4.y, p0);
        p0 = fmaf(fast_tanhf(h0.z + k4.z), w4.z, p0);
        p0 = fmaf(fast_tanhf(h0.w + k4.w), w4.w, p0);

        float p1 = 0.0f;
        if (has1) {
            p1 = fast_tanhf(h1.x + k4.x) * w4.x;
            p1 = fmaf(fast_tanhf(h1.y + k4.y), w4.y, p1);
            p1 = fmaf(fast_tanhf(h1.z + k4.z), w4.z, p1);
            p1 = fmaf(fast_tanhf(h1.w + k4.w), w4.w, p1);
        }

        #pragma unroll
        for (int off = 16; off > 0; off >>= 1) {
            p0 += __shfl_xor_sync(0xFFFFFFFFu, p0, off);
            p1 += __shfl_xor_sync(0xFFFFFFFFu, p1, off);
        }
        if (lane == 0) {
            s_scores[s0] = p0 + bias;
            if (has1) s_scores[s1] = p1 + bias;
        }
    }
    __syncthreads();

    // mask + softmax over S=200 (shfl reductions, 4 barriers)
    bool valid = false;
    float my_score = -INFINITY;
    if (tid < RD_S) {
        const int id = ids[(size_t)b * RD_S + tid];
        valid = (id != RD_PAD_ID) && (id != RD_INTEREST_ID);
        my_score = valid ? s_scores[tid] : -INFINITY;
    }

    float m = my_score;
    #pragma unroll
    for (int off = 16; off > 0; off >>= 1)
        m = fmaxf(m, __shfl_xor_sync(0xFFFFFFFFu, m, off));
    if (lane == 0) s_part[warp] = m;
    __syncthreads();
    if (warp == 0) {
        float v = (lane < RD_WARPS) ? s_part[lane] : -INFINITY;
        #pragma unroll
        for (int off = 4; off > 0; off >>= 1)
            v = fmaxf(v, __shfl_xor_sync(0xFFFFFFFFu, v, off));
        if (lane == 0) s_bcast = v;
    }
    __syncthreads();
    const float mx = s_bcast;

    const float e = valid ? __expf(my_score - mx) : 0.0f;
    float sum = e;
    #pragma unroll
    for (int off = 16; off > 0; off >>= 1)
        sum += __shfl_xor_sync(0xFFFFFFFFu, sum, off);
    if (lane == 0) s_part[warp] = sum;
    __syncthreads();
    if (warp == 0) {
        float v = (lane < RD_WARPS) ? s_part[lane] : 0.0f;
        #pragma unroll
        for (int off = 4; off > 0; off >>= 1)
            v += __shfl_xor_sync(0xFFFFFFFFu, v, off);
        if (lane == 0) s_bcast = v;
    }
    __syncthreads();

    if (tid < RD_S)
        g_wgt[(size_t)b * RD_S + tid] = e * (1.0f / s_bcast);
}

// ---------------------------------------------------------------------------
// Scatter: flat over B*S, runs after memset AND compute. ~2-3 us.
// ---------------------------------------------------------------------------
__global__ __launch_bounds__(RD_THREADS)
void rd_scatter_kernel(const int* __restrict__ ids,
                       float* __restrict__ out)
{
    const int i = blockIdx.x * RD_THREADS + threadIdx.x;
    if (i >= RD_B * RD_S) return;
    const int id = ids[i];
    if (id != RD_PAD_ID && id != RD_INTEREST_ID) {
        const int b = i / RD_S;
        atomicAdd(out + (size_t)b * RD_VOCAB + id, g_wgt[i]);
    }
}

extern "C" void kernel_launch(void* const* d_in, const int* in_sizes, int n_in,
                              void* d_out, int out_size)
{
    const float* hidden = (const float*)d_in[0];
    const int*   ids    = (const int*)d_in[1];
    const float* w_proj = (const float*)d_in[2];
    const float* b_proj = (const float*)d_in[3];
    float*       out    = (float*)d_out;

    // Lazily-created side stream + events (host-side objects only; the GPU
    // work issued per call is identical every call).
    static cudaStream_t s_side = nullptr;
    static cudaEvent_t  s_evFork = nullptr, s_evJoin = nullptr;
    if (s_side == nullptr) {
        cudaStreamCreateWithFlags(&s_side, cudaStreamNonBlocking);
        cudaEventCreateWithFlags(&s_evFork, cudaEventDisableTiming);
        cudaEventCreateWithFlags(&s_evJoin, cudaEventDisableTiming);
    }

    // Fork: side stream branches off the launch stream.
    cudaEventRecord(s_evFork, 0);
    cudaStreamWaitEvent(s_side, s_evFork, 0);

    // Branch A (side): zero the 409.6 MB output via the driver fill path.
    cudaMemsetAsync(out, 0, (size_t)RD_B * RD_VOCAB * sizeof(float), s_side);

    // Branch B (main, concurrent): scores -> softmax -> g_wgt.
    rd_compute_kernel<<<RD_B, RD_THREADS>>>(hidden, ids, w_proj, b_proj);

    // Join: main stream waits for the memset, then scatters.
    cudaEventRecord(s_evJoin, s_side);
    cudaStreamWaitEvent(0, s_evJoin, 0);

    rd_scatter_kernel<<<(RD_B * RD_S + RD_THREADS - 1) / RD_THREADS, RD_THREADS>>>(ids, out);
}